// round 4
// baseline (speedup 1.0000x reference)
#include <cuda_runtime.h>
#include <cstdint>

#define LN_EPS 1e-5f
#define NEG_SLOPE 0.2f
#define LOG2E 1.4426950408889634f

// ---------------- scratch (no allocations allowed) ----------------
#define Z1SZ (2048 * 128)
__device__ float g_z1p[4 * Z1SZ];    // split-K partials of x@W1^T
__device__ float g_h2[2048 * 64];    // after LN2+leaky
__device__ float g_h3[2048 * 32];    // after LN3+leaky
__device__ float g_M [2048 * 80];    // (h3 @ T) * log2(e)  [pre-scaled]
__device__ float g_ob[2048 * 5];     // pairwise accumulators

// ---------------- helpers ----------------
__device__ __forceinline__ unsigned long long f32x2_fma(unsigned long long a,
                                                        unsigned long long b,
                                                        unsigned long long c) {
    unsigned long long d;
    asm("fma.rn.f32x2 %0, %1, %2, %3;" : "=l"(d) : "l"(a), "l"(b), "l"(c));
    return d;
}
__device__ __forceinline__ unsigned long long f32x2_add(unsigned long long a,
                                                        unsigned long long b) {
    unsigned long long d;
    asm("add.rn.f32x2 %0, %1, %2;" : "=l"(d) : "l"(a), "l"(b));
    return d;
}
__device__ __forceinline__ float hadd2(unsigned long long a) {
    union { unsigned long long u; float2 f; } c; c.u = a;
    return c.f.x + c.f.y;
}
__device__ __forceinline__ float warp_sum32(float v) {
    v += __shfl_xor_sync(0xffffffffu, v, 16);
    v += __shfl_xor_sync(0xffffffffu, v, 8);
    v += __shfl_xor_sync(0xffffffffu, v, 4);
    v += __shfl_xor_sync(0xffffffffu, v, 2);
    v += __shfl_xor_sync(0xffffffffu, v, 1);
    return v;
}
__device__ __forceinline__ float leaky(float v) {
    return v >= 0.0f ? v : NEG_SLOPE * v;
}
__device__ __forceinline__ float ex2_approx(float v) {
    float r;
    asm("ex2.approx.f32 %0, %1;" : "=f"(r) : "f"(v));
    return r;
}

// =====================================================================
// Kernel 1: split-K GEMM  z1p[ks] = x @ W1^T  (K slice of 256)
// Tile 32x64, BK=32, 256 threads, thread tile 2x4, packed-k f32x2.
// grid (64, 2, 4) = 512 blocks
// =====================================================================
__global__ __launch_bounds__(256) void gemm1_kernel(
    const float* __restrict__ x, const float* __restrict__ W1) {
    __shared__ unsigned long long xs[16 * 32];   // [kp][row]
    __shared__ unsigned long long ws[16 * 64];   // [kp][col]

    const int t  = threadIdx.x;
    const int tx = t & 15;
    const int ty = t >> 4;
    const int i0 = blockIdx.x * 32;
    const int j0 = blockIdx.y * 64;
    const int kb = blockIdx.z * 256;

    unsigned long long acc[2][4];
#pragma unroll
    for (int r = 0; r < 2; r++)
#pragma unroll
        for (int c = 0; c < 4; c++) acc[r][c] = 0ULL;

    for (int kc = kb; kc < kb + 256; kc += 32) {
        {
            int row = t >> 3;
            int kq  = t & 7;
            float4 v = *reinterpret_cast<const float4*>(
                &x[(size_t)(i0 + row) * 1024 + kc + kq * 4]);
            union { float2 f; unsigned long long u; } p0, p1;
            p0.f = make_float2(v.x, v.y);
            p1.f = make_float2(v.z, v.w);
            xs[(2 * kq) * 32 + row]     = p0.u;
            xs[(2 * kq + 1) * 32 + row] = p1.u;
        }
#pragma unroll
        for (int u = 0; u < 2; u++) {
            int fi   = t + 256 * u;
            int wrow = fi >> 3;
            int kq   = fi & 7;
            float4 v = *reinterpret_cast<const float4*>(
                &W1[(size_t)(j0 + wrow) * 1024 + kc + kq * 4]);
            union { float2 f; unsigned long long u; } p0, p1;
            p0.f = make_float2(v.x, v.y);
            p1.f = make_float2(v.z, v.w);
            ws[(2 * kq) * 64 + wrow]     = p0.u;
            ws[(2 * kq + 1) * 64 + wrow] = p1.u;
        }
        __syncthreads();

#pragma unroll
        for (int kp = 0; kp < 16; kp++) {
            unsigned long long a2[2], b2[4];
#pragma unroll
            for (int r = 0; r < 2; r++) a2[r] = xs[kp * 32 + ty + 16 * r];
#pragma unroll
            for (int c = 0; c < 4; c++) b2[c] = ws[kp * 64 + tx + 16 * c];
#pragma unroll
            for (int r = 0; r < 2; r++)
#pragma unroll
                for (int c = 0; c < 4; c++)
                    acc[r][c] = f32x2_fma(a2[r], b2[c], acc[r][c]);
        }
        __syncthreads();
    }

    float* out = &g_z1p[(size_t)blockIdx.z * Z1SZ];
#pragma unroll
    for (int r = 0; r < 2; r++) {
        int row = i0 + ty + 16 * r;
#pragma unroll
        for (int c = 0; c < 4; c++) {
            int col = j0 + tx + 16 * c;
            out[(size_t)row * 128 + col] = hadd2(acc[r][c]);
        }
    }
}

// =====================================================================
// Kernel 2a: z1 = sum(partials)+b1 ; h1 = leaky(LN(z1));
//            z2 = h1@W2^T + b2 ; h2 = leaky(LN(z2))
// one warp per row, 4 warps/block, grid 512
// =====================================================================
__global__ __launch_bounds__(128) void enc2a_kernel(
    const float* __restrict__ b1,
    const float* __restrict__ g1, const float* __restrict__ be1,
    const float* __restrict__ W2, const float* __restrict__ b2,
    const float* __restrict__ g2, const float* __restrict__ be2) {
    __shared__ float w2s[128 * 64];      // [k][pair-interleaved cols]
    __shared__ float h1s[4][128];

    const int t = threadIdx.x;
    for (int idx = t; idx < 8192; idx += 128) {
        int col = idx >> 7;
        int k   = idx & 127;
        w2s[k * 64 + (col & 31) * 2 + (col >> 5)] = W2[idx];
    }
    __syncthreads();

    const int lane = t & 31;
    const int w    = t >> 5;
    const int row  = blockIdx.x * 4 + w;
    const size_t off = (size_t)row * 128 + lane * 4;

    // ---- sum split-K partials + bias ----
    float4 p0 = *reinterpret_cast<const float4*>(&g_z1p[0 * Z1SZ + off]);
    float4 p1 = *reinterpret_cast<const float4*>(&g_z1p[1 * Z1SZ + off]);
    float4 p2 = *reinterpret_cast<const float4*>(&g_z1p[2 * Z1SZ + off]);
    float4 p3 = *reinterpret_cast<const float4*>(&g_z1p[3 * Z1SZ + off]);
    float4 bb = *reinterpret_cast<const float4*>(&b1[lane * 4]);
    float4 zv;
    zv.x = (p0.x + p1.x) + (p2.x + p3.x) + bb.x;
    zv.y = (p0.y + p1.y) + (p2.y + p3.y) + bb.y;
    zv.z = (p0.z + p1.z) + (p2.z + p3.z) + bb.z;
    zv.w = (p0.w + p1.w) + (p2.w + p3.w) + bb.w;

    // ---- LN1 + leaky ----
    float s  = zv.x + zv.y + zv.z + zv.w;
    float sq = zv.x * zv.x + zv.y * zv.y + zv.z * zv.z + zv.w * zv.w;
    s  = warp_sum32(s);
    sq = warp_sum32(sq);
    float mu   = s * (1.0f / 128.0f);
    float var  = sq * (1.0f / 128.0f) - mu * mu;
    float rstd = rsqrtf(var + LN_EPS);
    float4 gv  = *reinterpret_cast<const float4*>(&g1[lane * 4]);
    float4 bv  = *reinterpret_cast<const float4*>(&be1[lane * 4]);
    h1s[w][lane * 4 + 0] = leaky((zv.x - mu) * rstd * gv.x + bv.x);
    h1s[w][lane * 4 + 1] = leaky((zv.y - mu) * rstd * gv.y + bv.y);
    h1s[w][lane * 4 + 2] = leaky((zv.z - mu) * rstd * gv.z + bv.z);
    h1s[w][lane * 4 + 3] = leaky((zv.w - mu) * rstd * gv.w + bv.w);
    __syncwarp();

    // ---- GEMM2: 2 cols per lane, 4 partials each ----
    float pa0 = 0.f, pa1 = 0.f, pa2 = 0.f, pa3 = 0.f;
    float pb0 = 0.f, pb1 = 0.f, pb2 = 0.f, pb3 = 0.f;
#pragma unroll
    for (int k4 = 0; k4 < 128; k4 += 4) {
        float4 hv = *reinterpret_cast<const float4*>(&h1s[w][k4]);
        float2 w0 = *reinterpret_cast<const float2*>(&w2s[(k4 + 0) * 64 + lane * 2]);
        float2 w1 = *reinterpret_cast<const float2*>(&w2s[(k4 + 1) * 64 + lane * 2]);
        float2 w2v = *reinterpret_cast<const float2*>(&w2s[(k4 + 2) * 64 + lane * 2]);
        float2 w3 = *reinterpret_cast<const float2*>(&w2s[(k4 + 3) * 64 + lane * 2]);
        pa0 += hv.x * w0.x;  pb0 += hv.x * w0.y;
        pa1 += hv.y * w1.x;  pb1 += hv.y * w1.y;
        pa2 += hv.z * w2v.x; pb2 += hv.z * w2v.y;
        pa3 += hv.w * w3.x;  pb3 += hv.w * w3.y;
    }
    float z2a = (pa0 + pa1) + (pa2 + pa3) + b2[lane];
    float z2b = (pb0 + pb1) + (pb2 + pb3) + b2[lane + 32];

    // ---- LN2 + leaky ----
    float s2  = warp_sum32(z2a + z2b);
    float sq2 = warp_sum32(z2a * z2a + z2b * z2b);
    float mu2   = s2 * (1.0f / 64.0f);
    float var2  = sq2 * (1.0f / 64.0f) - mu2 * mu2;
    float rstd2 = rsqrtf(var2 + LN_EPS);
    g_h2[(size_t)row * 64 + lane]      = leaky((z2a - mu2) * rstd2 * g2[lane] + be2[lane]);
    g_h2[(size_t)row * 64 + lane + 32] = leaky((z2b - mu2) * rstd2 * g2[lane + 32] + be2[lane + 32]);
}

// =====================================================================
// Kernel 2b: z3 = h2@W3^T + b3 ; h3 = leaky(LN(z3)) ; M = (h3 @ T)*log2e
// Also zeroes g_ob. one warp per row, 4 warps/block, grid 512
// =====================================================================
__global__ __launch_bounds__(128) void enc2b_kernel(
    const float* __restrict__ W3, const float* __restrict__ b3,
    const float* __restrict__ g3, const float* __restrict__ be3,
    const float* __restrict__ T) {
    __shared__ float w3t[64 * 32];   // [k][c]
    __shared__ float Ts[32 * 80];    // [k][c]
    __shared__ float h2s[4][64];
    __shared__ float h3s[4][32];

    const int t = threadIdx.x;
    if (t < 20) g_ob[blockIdx.x * 20 + t] = 0.0f;

    for (int idx = t; idx < 2048; idx += 128) {
        int c = idx >> 6;
        int k = idx & 63;
        w3t[k * 32 + c] = W3[idx];
    }
    for (int idx = t; idx < 2560; idx += 128) Ts[idx] = T[idx];
    __syncthreads();

    const int lane = t & 31;
    const int w    = t >> 5;
    const int row  = blockIdx.x * 4 + w;

    float2 h2v = *reinterpret_cast<const float2*>(&g_h2[(size_t)row * 64 + lane * 2]);
    h2s[w][lane * 2]     = h2v.x;
    h2s[w][lane * 2 + 1] = h2v.y;
    __syncwarp();

    float q0 = 0.f, q1 = 0.f, q2 = 0.f, q3 = 0.f;
#pragma unroll
    for (int k = 0; k < 64; k += 4) {
        q0 += h2s[w][k + 0] * w3t[(k + 0) * 32 + lane];
        q1 += h2s[w][k + 1] * w3t[(k + 1) * 32 + lane];
        q2 += h2s[w][k + 2] * w3t[(k + 2) * 32 + lane];
        q3 += h2s[w][k + 3] * w3t[(k + 3) * 32 + lane];
    }
    float z3 = (q0 + q1) + (q2 + q3) + b3[lane];

    float s3  = warp_sum32(z3);
    float sq3 = warp_sum32(z3 * z3);
    float mu3   = s3 * (1.0f / 32.0f);
    float var3  = sq3 * (1.0f / 32.0f) - mu3 * mu3;
    float rstd3 = rsqrtf(var3 + LN_EPS);
    float h3v = leaky((z3 - mu3) * rstd3 * g3[lane] + be3[lane]);
    g_h3[(size_t)row * 32 + lane] = h3v;
    h3s[w][lane] = h3v;
    __syncwarp();

    for (int c = lane; c < 80; c += 32) {
        float m0 = 0.f, m1 = 0.f;
#pragma unroll
        for (int k = 0; k < 32; k += 2) {
            m0 += h3s[w][k]     * Ts[k * 80 + c];
            m1 += h3s[w][k + 1] * Ts[(k + 1) * 80 + c];
        }
        g_M[(size_t)row * 80 + c] = (m0 + m1) * LOG2E;   // pre-scale for ex2
    }
}

// =====================================================================
// Kernel 4: pairwise, one-wave persistent layout.
// 740 blocks = 148 SM x 5 = 20 (i_blk,o) groups x 37 j-chunks.
// Each block: fixed (i_blk, o), contiguous j chunk of <=56.
// 128 threads, PW_I=4 (i = i_blk*512 + ii*128 + t).
// es kept in regs over whole chunk -> ONE atomicAdd per (thread, ii).
// =====================================================================
#define PW_THREADS 128
#define PW_I 4
#define PW_CHUNK 56
#define ABSM 0x7FFFFFFF7FFFFFFFULL

__global__ __launch_bounds__(PW_THREADS, 5) void pairwise_kernel() {
    __shared__ unsigned long long mjneg[PW_CHUNK * 8];

    const int bid = blockIdx.x;
    const int g   = bid / 37;          // 0..19
    const int c   = bid % 37;          // j chunk
    const int i_blk = g / 5;           // 0..3
    const int o     = g % 5;
    const int j0    = c * PW_CHUNK;
    const int jcount = min(PW_CHUNK, 2048 - j0);
    const int t = threadIdx.x;

    for (int idx = t; idx < jcount * 8; idx += PW_THREADS) {
        int jj = idx >> 3;
        int p  = idx & 7;
        float2 v = *reinterpret_cast<const float2*>(
            &g_M[(size_t)(j0 + jj) * 80 + o * 16 + p * 2]);
        union { float2 f; unsigned long long u; } cv;
        cv.f = make_float2(-v.x, -v.y);
        mjneg[jj * 8 + p] = cv.u;
    }

    unsigned long long mi[PW_I][8];
#pragma unroll
    for (int ii = 0; ii < PW_I; ii++) {
        int i = i_blk * 512 + ii * PW_THREADS + t;
#pragma unroll
        for (int p = 0; p < 8; p++)
            mi[ii][p] = *reinterpret_cast<const unsigned long long*>(
                &g_M[(size_t)i * 80 + o * 16 + p * 2]);
    }
    __syncthreads();

    float es[PW_I];
#pragma unroll
    for (int ii = 0; ii < PW_I; ii++) es[ii] = 0.f;

    for (int jj = 0; jj < jcount; jj++) {
        unsigned long long mj[8];
#pragma unroll
        for (int p = 0; p < 8; p++) mj[p] = mjneg[jj * 8 + p];
#pragma unroll
        for (int ii = 0; ii < PW_I; ii++) {
            unsigned long long a0 = 0ULL, a1 = 0ULL;
#pragma unroll
            for (int p = 0; p < 8; p += 2) {
                unsigned long long d0 = f32x2_add(mi[ii][p],     mj[p]);
                unsigned long long d1 = f32x2_add(mi[ii][p + 1], mj[p + 1]);
                a0 = f32x2_add(a0, d0 & ABSM);
                a1 = f32x2_add(a1, d1 & ABSM);
            }
            unsigned long long at = f32x2_add(a0, a1);
            union { unsigned long long u; float2 f; } cc; cc.u = at;
            float nl1 = -cc.f.x - cc.f.y;
            es[ii] += ex2_approx(nl1);
        }
    }
#pragma unroll
    for (int ii = 0; ii < PW_I; ii++) {
        int i = i_blk * 512 + ii * PW_THREADS + t;
        atomicAdd(&g_ob[i * 5 + o], es[ii]);
    }
}

// =====================================================================
// Kernel 5: out[i] = bf + Wf[0:32].h3[i] + Wf[32:37].(ob[i]-1)
// =====================================================================
__global__ void final_kernel(const float* __restrict__ Wf,
                             const float* __restrict__ bf,
                             float* __restrict__ out) {
    int i = blockIdx.x * blockDim.x + threadIdx.x;
    if (i >= 2048) return;
    float s = bf[0];
#pragma unroll
    for (int c = 0; c < 32; c++) s += g_h3[(size_t)i * 32 + c] * Wf[c];
#pragma unroll
    for (int oo = 0; oo < 5; oo++) s += (g_ob[i * 5 + oo] - 1.0f) * Wf[32 + oo];
    out[i] = s;
}

// =====================================================================
extern "C" void kernel_launch(void* const* d_in, const int* in_sizes, int n_in,
                              void* d_out, int out_size) {
    (void)in_sizes; (void)n_in; (void)out_size;
    const float* x   = (const float*)d_in[0];
    const float* W1  = (const float*)d_in[1];
    const float* b1  = (const float*)d_in[2];
    const float* g1  = (const float*)d_in[3];
    const float* be1 = (const float*)d_in[4];
    const float* W2  = (const float*)d_in[5];
    const float* b2  = (const float*)d_in[6];
    const float* g2  = (const float*)d_in[7];
    const float* be2 = (const float*)d_in[8];
    const float* W3  = (const float*)d_in[9];
    const float* b3  = (const float*)d_in[10];
    const float* g3  = (const float*)d_in[11];
    const float* be3 = (const float*)d_in[12];
    const float* T   = (const float*)d_in[13];
    const float* Wf  = (const float*)d_in[14];
    const float* bf  = (const float*)d_in[15];
    float* out = (float*)d_out;

    gemm1_kernel<<<dim3(64, 2, 4), 256>>>(x, W1);
    enc2a_kernel<<<512, 128>>>(b1, g1, be1, W2, b2, g2, be2);
    enc2b_kernel<<<512, 128>>>(W3, b3, g3, be3, T);
    pairwise_kernel<<<740, PW_THREADS>>>();
    final_kernel<<<8, 256>>>(Wf, bf, out);
}

// round 5
// speedup vs baseline: 1.1701x; 1.1701x over previous
#include <cuda_runtime.h>
#include <cstdint>

#define LN_EPS 1e-5f
#define NEG_SLOPE 0.2f
#define LOG2E 1.4426950408889634f

// ---------------- scratch (no allocations allowed) ----------------
#define Z1SZ (2048 * 128)
__device__ float g_z1p[2 * Z1SZ];    // split-K partials of x@W1^T
__device__ float g_h2[2048 * 64];    // after LN2+leaky
__device__ float g_h3[2048 * 32];    // after LN3+leaky
__device__ float g_M [2048 * 80];    // (h3 @ T) * log2(e)  [pre-scaled]
__device__ float g_ob[2048 * 5];     // pairwise accumulators (no self term)

// ---------------- helpers ----------------
__device__ __forceinline__ unsigned long long f32x2_fma(unsigned long long a,
                                                        unsigned long long b,
                                                        unsigned long long c) {
    unsigned long long d;
    asm("fma.rn.f32x2 %0, %1, %2, %3;" : "=l"(d) : "l"(a), "l"(b), "l"(c));
    return d;
}
__device__ __forceinline__ unsigned long long f32x2_add(unsigned long long a,
                                                        unsigned long long b) {
    unsigned long long d;
    asm("add.rn.f32x2 %0, %1, %2;" : "=l"(d) : "l"(a), "l"(b));
    return d;
}
__device__ __forceinline__ float hadd2(unsigned long long a) {
    union { unsigned long long u; float2 f; } c; c.u = a;
    return c.f.x + c.f.y;
}
__device__ __forceinline__ float warp_sum32(float v) {
    v += __shfl_xor_sync(0xffffffffu, v, 16);
    v += __shfl_xor_sync(0xffffffffu, v, 8);
    v += __shfl_xor_sync(0xffffffffu, v, 4);
    v += __shfl_xor_sync(0xffffffffu, v, 2);
    v += __shfl_xor_sync(0xffffffffu, v, 1);
    return v;
}
__device__ __forceinline__ float leaky(float v) {
    return v >= 0.0f ? v : NEG_SLOPE * v;
}
__device__ __forceinline__ float ex2_approx(float v) {
    float r;
    asm("ex2.approx.f32 %0, %1;" : "=f"(r) : "f"(v));
    return r;
}

// =====================================================================
// Kernel 1: split-K GEMM  z1p[ks] = x @ W1^T  (K slice of 512)
// Tile 32x64, BK=32, 256 threads, thread tile 2x4, packed-k f32x2.
// grid (64, 2, 2) = 256 blocks
// =====================================================================
__global__ __launch_bounds__(256) void gemm1_kernel(
    const float* __restrict__ x, const float* __restrict__ W1) {
    __shared__ unsigned long long xs[16 * 32];   // [kp][row]
    __shared__ unsigned long long ws[16 * 64];   // [kp][col]

    const int t  = threadIdx.x;
    const int tx = t & 15;
    const int ty = t >> 4;
    const int i0 = blockIdx.x * 32;
    const int j0 = blockIdx.y * 64;
    const int kb = blockIdx.z * 512;

    unsigned long long acc[2][4];
#pragma unroll
    for (int r = 0; r < 2; r++)
#pragma unroll
        for (int c = 0; c < 4; c++) acc[r][c] = 0ULL;

    for (int kc = kb; kc < kb + 512; kc += 32) {
        {
            int row = t >> 3;
            int kq  = t & 7;
            float4 v = *reinterpret_cast<const float4*>(
                &x[(size_t)(i0 + row) * 1024 + kc + kq * 4]);
            union { float2 f; unsigned long long u; } p0, p1;
            p0.f = make_float2(v.x, v.y);
            p1.f = make_float2(v.z, v.w);
            xs[(2 * kq) * 32 + row]     = p0.u;
            xs[(2 * kq + 1) * 32 + row] = p1.u;
        }
#pragma unroll
        for (int u = 0; u < 2; u++) {
            int fi   = t + 256 * u;
            int wrow = fi >> 3;
            int kq   = fi & 7;
            float4 v = *reinterpret_cast<const float4*>(
                &W1[(size_t)(j0 + wrow) * 1024 + kc + kq * 4]);
            union { float2 f; unsigned long long u; } p0, p1;
            p0.f = make_float2(v.x, v.y);
            p1.f = make_float2(v.z, v.w);
            ws[(2 * kq) * 64 + wrow]     = p0.u;
            ws[(2 * kq + 1) * 64 + wrow] = p1.u;
        }
        __syncthreads();

#pragma unroll
        for (int kp = 0; kp < 16; kp++) {
            unsigned long long a2[2], b2[4];
#pragma unroll
            for (int r = 0; r < 2; r++) a2[r] = xs[kp * 32 + ty + 16 * r];
#pragma unroll
            for (int c = 0; c < 4; c++) b2[c] = ws[kp * 64 + tx + 16 * c];
#pragma unroll
            for (int r = 0; r < 2; r++)
#pragma unroll
                for (int c = 0; c < 4; c++)
                    acc[r][c] = f32x2_fma(a2[r], b2[c], acc[r][c]);
        }
        __syncthreads();
    }

    float* out = &g_z1p[(size_t)blockIdx.z * Z1SZ];
#pragma unroll
    for (int r = 0; r < 2; r++) {
        int row = i0 + ty + 16 * r;
#pragma unroll
        for (int c = 0; c < 4; c++) {
            int col = j0 + tx + 16 * c;
            out[(size_t)row * 128 + col] = hadd2(acc[r][c]);
        }
    }
}

// =====================================================================
// Kernel 2a: z1 = p0+p1+b1 ; h1 = leaky(LN(z1));
//            z2 = h1@W2^T + b2 ; h2 = leaky(LN(z2))
// one warp per row, 8 warps/block, grid 256
// =====================================================================
__global__ __launch_bounds__(256) void enc2a_kernel(
    const float* __restrict__ b1,
    const float* __restrict__ g1, const float* __restrict__ be1,
    const float* __restrict__ W2, const float* __restrict__ b2,
    const float* __restrict__ g2, const float* __restrict__ be2) {
    __shared__ float w2s[128 * 64];      // [k][pair-interleaved cols]
    __shared__ float h1s[8][128];

    const int t = threadIdx.x;
    for (int idx = t; idx < 8192; idx += 256) {
        int col = idx >> 7;
        int k   = idx & 127;
        w2s[k * 64 + (col & 31) * 2 + (col >> 5)] = W2[idx];
    }
    __syncthreads();

    const int lane = t & 31;
    const int w    = t >> 5;
    const int row  = blockIdx.x * 8 + w;
    const size_t off = (size_t)row * 128 + lane * 4;

    float4 p0 = *reinterpret_cast<const float4*>(&g_z1p[off]);
    float4 p1 = *reinterpret_cast<const float4*>(&g_z1p[Z1SZ + off]);
    float4 bb = *reinterpret_cast<const float4*>(&b1[lane * 4]);
    float4 zv;
    zv.x = p0.x + p1.x + bb.x;
    zv.y = p0.y + p1.y + bb.y;
    zv.z = p0.z + p1.z + bb.z;
    zv.w = p0.w + p1.w + bb.w;

    // ---- LN1 + leaky ----
    float s  = zv.x + zv.y + zv.z + zv.w;
    float sq = zv.x * zv.x + zv.y * zv.y + zv.z * zv.z + zv.w * zv.w;
    s  = warp_sum32(s);
    sq = warp_sum32(sq);
    float mu   = s * (1.0f / 128.0f);
    float var  = sq * (1.0f / 128.0f) - mu * mu;
    float rstd = rsqrtf(var + LN_EPS);
    float4 gv  = *reinterpret_cast<const float4*>(&g1[lane * 4]);
    float4 bv  = *reinterpret_cast<const float4*>(&be1[lane * 4]);
    h1s[w][lane * 4 + 0] = leaky((zv.x - mu) * rstd * gv.x + bv.x);
    h1s[w][lane * 4 + 1] = leaky((zv.y - mu) * rstd * gv.y + bv.y);
    h1s[w][lane * 4 + 2] = leaky((zv.z - mu) * rstd * gv.z + bv.z);
    h1s[w][lane * 4 + 3] = leaky((zv.w - mu) * rstd * gv.w + bv.w);
    __syncwarp();

    // ---- GEMM2: 2 cols per lane, 4 partials each ----
    float pa0 = 0.f, pa1 = 0.f, pa2 = 0.f, pa3 = 0.f;
    float pb0 = 0.f, pb1 = 0.f, pb2 = 0.f, pb3 = 0.f;
#pragma unroll
    for (int k4 = 0; k4 < 128; k4 += 4) {
        float4 hv = *reinterpret_cast<const float4*>(&h1s[w][k4]);
        float2 w0 = *reinterpret_cast<const float2*>(&w2s[(k4 + 0) * 64 + lane * 2]);
        float2 w1 = *reinterpret_cast<const float2*>(&w2s[(k4 + 1) * 64 + lane * 2]);
        float2 w2v = *reinterpret_cast<const float2*>(&w2s[(k4 + 2) * 64 + lane * 2]);
        float2 w3 = *reinterpret_cast<const float2*>(&w2s[(k4 + 3) * 64 + lane * 2]);
        pa0 += hv.x * w0.x;  pb0 += hv.x * w0.y;
        pa1 += hv.y * w1.x;  pb1 += hv.y * w1.y;
        pa2 += hv.z * w2v.x; pb2 += hv.z * w2v.y;
        pa3 += hv.w * w3.x;  pb3 += hv.w * w3.y;
    }
    float z2a = (pa0 + pa1) + (pa2 + pa3) + b2[lane];
    float z2b = (pb0 + pb1) + (pb2 + pb3) + b2[lane + 32];

    // ---- LN2 + leaky ----
    float s2  = warp_sum32(z2a + z2b);
    float sq2 = warp_sum32(z2a * z2a + z2b * z2b);
    float mu2   = s2 * (1.0f / 64.0f);
    float var2  = sq2 * (1.0f / 64.0f) - mu2 * mu2;
    float rstd2 = rsqrtf(var2 + LN_EPS);
    g_h2[(size_t)row * 64 + lane]      = leaky((z2a - mu2) * rstd2 * g2[lane] + be2[lane]);
    g_h2[(size_t)row * 64 + lane + 32] = leaky((z2b - mu2) * rstd2 * g2[lane + 32] + be2[lane + 32]);
}

// =====================================================================
// Kernel 2b: z3 = h2@W3^T + b3 ; h3 = leaky(LN(z3)) ; M = (h3 @ T)*log2e
// Also zeroes g_ob. one warp per row, 8 warps/block, grid 256
// =====================================================================
__global__ __launch_bounds__(256) void enc2b_kernel(
    const float* __restrict__ W3, const float* __restrict__ b3,
    const float* __restrict__ g3, const float* __restrict__ be3,
    const float* __restrict__ T) {
    __shared__ float w3t[64 * 32];   // [k][c]
    __shared__ float Ts[32 * 80];    // [k][c]
    __shared__ float h2s[8][64];
    __shared__ float h3s[8][32];

    const int t = threadIdx.x;
    if (t < 40) g_ob[blockIdx.x * 40 + t] = 0.0f;

    for (int idx = t; idx < 2048; idx += 256) {
        int c = idx >> 6;
        int k = idx & 63;
        w3t[k * 32 + c] = W3[idx];
    }
    for (int idx = t; idx < 2560; idx += 256) Ts[idx] = T[idx];
    __syncthreads();

    const int lane = t & 31;
    const int w    = t >> 5;
    const int row  = blockIdx.x * 8 + w;

    float2 h2v = *reinterpret_cast<const float2*>(&g_h2[(size_t)row * 64 + lane * 2]);
    h2s[w][lane * 2]     = h2v.x;
    h2s[w][lane * 2 + 1] = h2v.y;
    __syncwarp();

    float q0 = 0.f, q1 = 0.f, q2 = 0.f, q3 = 0.f;
#pragma unroll
    for (int k = 0; k < 64; k += 4) {
        q0 += h2s[w][k + 0] * w3t[(k + 0) * 32 + lane];
        q1 += h2s[w][k + 1] * w3t[(k + 1) * 32 + lane];
        q2 += h2s[w][k + 2] * w3t[(k + 2) * 32 + lane];
        q3 += h2s[w][k + 3] * w3t[(k + 3) * 32 + lane];
    }
    float z3 = (q0 + q1) + (q2 + q3) + b3[lane];

    float s3  = warp_sum32(z3);
    float sq3 = warp_sum32(z3 * z3);
    float mu3   = s3 * (1.0f / 32.0f);
    float var3  = sq3 * (1.0f / 32.0f) - mu3 * mu3;
    float rstd3 = rsqrtf(var3 + LN_EPS);
    float h3v = leaky((z3 - mu3) * rstd3 * g3[lane] + be3[lane]);
    g_h3[(size_t)row * 32 + lane] = h3v;
    h3s[w][lane] = h3v;
    __syncwarp();

    for (int c = lane; c < 80; c += 32) {
        float m0 = 0.f, m1 = 0.f;
#pragma unroll
        for (int k = 0; k < 32; k += 2) {
            m0 += h3s[w][k]     * Ts[k * 80 + c];
            m1 += h3s[w][k + 1] * Ts[(k + 1) * 80 + c];
        }
        g_M[(size_t)row * 80 + c] = (m0 + m1) * LOG2E;   // pre-scale for ex2
    }
}

// =====================================================================
// Kernel 4: SYMMETRIC pairwise. Each unordered pair computed once.
// 16 i-tiles x 16 j-tiles upper triangle = 136 pairs x 5 o = 680 blocks.
// 128 threads: thread t owns row i = i0+t (mi in regs), loops 128 j's
// from smem. exp contributes to row acc (reg) and col acc (5-shfl
// warp reduce -> colacc[w][jj]). Diagonal tiles: only jj > t.
// Self-pair excluded => reference's "-1" cancels (final kernel: no -1).
// =====================================================================
#define ABSM 0x7FFFFFFF7FFFFFFFULL

__global__ __launch_bounds__(128) void pairwise_kernel() {
    __shared__ unsigned long long mjneg[128 * 8];
    __shared__ float colacc[4][128];

    const int bid = blockIdx.x;
    const int o   = bid % 5;
    int p = bid / 5;                 // 0..135 upper-triangle pair index
    int it = 0;
    while (p >= 16 - it) { p -= 16 - it; it++; }
    const int jt = it + p;
    const bool diag = (it == jt);
    const int i0 = it * 128;
    const int j0 = jt * 128;
    const int t  = threadIdx.x;
    const int lane = t & 31;
    const int w    = t >> 5;

    // stage j-tile negated
    for (int idx = t; idx < 1024; idx += 128) {
        int jj = idx >> 3;
        int pp = idx & 7;
        float2 v = *reinterpret_cast<const float2*>(
            &g_M[(size_t)(j0 + jj) * 80 + o * 16 + pp * 2]);
        union { float2 f; unsigned long long u; } cv;
        cv.f = make_float2(-v.x, -v.y);
        mjneg[jj * 8 + pp] = cv.u;
    }

    unsigned long long mi[8];
#pragma unroll
    for (int pp = 0; pp < 8; pp++)
        mi[pp] = *reinterpret_cast<const unsigned long long*>(
            &g_M[(size_t)(i0 + t) * 80 + o * 16 + pp * 2]);
    __syncthreads();

    float es = 0.f;
#pragma unroll 2
    for (int jj = 0; jj < 128; jj++) {
        unsigned long long a0 = 0ULL, a1 = 0ULL;
#pragma unroll
        for (int pp = 0; pp < 8; pp += 2) {
            unsigned long long d0 = f32x2_add(mi[pp],     mjneg[jj * 8 + pp]);
            unsigned long long d1 = f32x2_add(mi[pp + 1], mjneg[jj * 8 + pp + 1]);
            a0 = f32x2_add(a0, d0 & ABSM);
            a1 = f32x2_add(a1, d1 & ABSM);
        }
        unsigned long long at = f32x2_add(a0, a1);
        union { unsigned long long u; float2 f; } cc; cc.u = at;
        float nl1 = -cc.f.x - cc.f.y;
        float e = ex2_approx(nl1);
        if (diag && jj <= t) e = 0.f;       // strict upper triangle only
        es += e;
        // lane reduction for column jj
        float cs = e;
        cs += __shfl_xor_sync(0xffffffffu, cs, 16);
        cs += __shfl_xor_sync(0xffffffffu, cs, 8);
        cs += __shfl_xor_sync(0xffffffffu, cs, 4);
        cs += __shfl_xor_sync(0xffffffffu, cs, 2);
        cs += __shfl_xor_sync(0xffffffffu, cs, 1);
        if (lane == 0) colacc[w][jj] = cs;
    }
    // row contribution
    atomicAdd(&g_ob[(i0 + t) * 5 + o], es);
    __syncthreads();
    // column contribution: thread t sums 4 warps' col t
    float cs = colacc[0][t] + colacc[1][t] + colacc[2][t] + colacc[3][t];
    atomicAdd(&g_ob[(j0 + t) * 5 + o], cs);
}

// =====================================================================
// Kernel 5: out[i] = bf + Wf[0:32].h3[i] + Wf[32:37].ob[i]
// (ob already excludes the self term)
// =====================================================================
__global__ void final_kernel(const float* __restrict__ Wf,
                             const float* __restrict__ bf,
                             float* __restrict__ out) {
    int i = blockIdx.x * blockDim.x + threadIdx.x;
    if (i >= 2048) return;
    float s = bf[0];
#pragma unroll
    for (int c = 0; c < 32; c++) s += g_h3[(size_t)i * 32 + c] * Wf[c];
#pragma unroll
    for (int oo = 0; oo < 5; oo++) s += g_ob[i * 5 + oo] * Wf[32 + oo];
    out[i] = s;
}

// =====================================================================
extern "C" void kernel_launch(void* const* d_in, const int* in_sizes, int n_in,
                              void* d_out, int out_size) {
    (void)in_sizes; (void)n_in; (void)out_size;
    const float* x   = (const float*)d_in[0];
    const float* W1  = (const float*)d_in[1];
    const float* b1  = (const float*)d_in[2];
    const float* g1  = (const float*)d_in[3];
    const float* be1 = (const float*)d_in[4];
    const float* W2  = (const float*)d_in[5];
    const float* b2  = (const float*)d_in[6];
    const float* g2  = (const float*)d_in[7];
    const float* be2 = (const float*)d_in[8];
    const float* W3  = (const float*)d_in[9];
    const float* b3  = (const float*)d_in[10];
    const float* g3  = (const float*)d_in[11];
    const float* be3 = (const float*)d_in[12];
    const float* T   = (const float*)d_in[13];
    const float* Wf  = (const float*)d_in[14];
    const float* bf  = (const float*)d_in[15];
    float* out = (float*)d_out;

    gemm1_kernel<<<dim3(64, 2, 2), 256>>>(x, W1);
    enc2a_kernel<<<256, 256>>>(b1, g1, be1, W2, b2, g2, be2);
    enc2b_kernel<<<256, 256>>>(W3, b3, g3, be3, T);
    pairwise_kernel<<<680, 128>>>();
    final_kernel<<<8, 256>>>(Wf, bf, out);
}

// round 6
// speedup vs baseline: 1.2828x; 1.0963x over previous
#include <cuda_runtime.h>
#include <cstdint>

#define LN_EPS 1e-5f
#define NEG_SLOPE 0.2f
#define LOG2E 1.4426950408889634f

// ---------------- scratch (no allocations allowed) ----------------
#define Z1SZ (2048 * 128)
__device__ float g_z1p[4 * Z1SZ];    // split-K partials of x@W1^T
__device__ float g_h2[2048 * 64];    // after LN2+leaky
__device__ float g_h3[2048 * 32];    // after LN3+leaky
__device__ float g_M [2048 * 80];    // (h3 @ T) * log2(e)  [pre-scaled]
__device__ float g_ob[2048 * 5];     // pairwise accumulators (no self term)

// ---------------- helpers ----------------
__device__ __forceinline__ unsigned long long f32x2_fma(unsigned long long a,
                                                        unsigned long long b,
                                                        unsigned long long c) {
    unsigned long long d;
    asm("fma.rn.f32x2 %0, %1, %2, %3;" : "=l"(d) : "l"(a), "l"(b), "l"(c));
    return d;
}
__device__ __forceinline__ unsigned long long f32x2_add(unsigned long long a,
                                                        unsigned long long b) {
    unsigned long long d;
    asm("add.rn.f32x2 %0, %1, %2;" : "=l"(d) : "l"(a), "l"(b));
    return d;
}
__device__ __forceinline__ float hadd2(unsigned long long a) {
    union { unsigned long long u; float2 f; } c; c.u = a;
    return c.f.x + c.f.y;
}
__device__ __forceinline__ float warp_sum32(float v) {
    v += __shfl_xor_sync(0xffffffffu, v, 16);
    v += __shfl_xor_sync(0xffffffffu, v, 8);
    v += __shfl_xor_sync(0xffffffffu, v, 4);
    v += __shfl_xor_sync(0xffffffffu, v, 2);
    v += __shfl_xor_sync(0xffffffffu, v, 1);
    return v;
}
__device__ __forceinline__ float leaky(float v) {
    return v >= 0.0f ? v : NEG_SLOPE * v;
}
__device__ __forceinline__ float ex2_approx(float v) {
    float r;
    asm("ex2.approx.f32 %0, %1;" : "=f"(r) : "f"(v));
    return r;
}

// =====================================================================
// Kernel 1: split-K GEMM  z1p[ks] = x @ W1^T  (K slice of 256)
// Tile 32x64, BK=32, 128 threads (8x16), thread tile 4x4, packed f32x2.
// LDS:FMA = 8:16 per kp (FMA-pipe bound).  grid (64, 2, 4) = 512 blocks
// =====================================================================
__global__ __launch_bounds__(128) void gemm1_kernel(
    const float* __restrict__ x, const float* __restrict__ W1) {
    __shared__ unsigned long long xs[16 * 32];   // [kp][row]
    __shared__ unsigned long long ws[16 * 64];   // [kp][col]

    const int t  = threadIdx.x;
    const int tx = t & 15;          // col group
    const int ty = t >> 4;          // row group
    const int i0 = blockIdx.x * 32;
    const int j0 = blockIdx.y * 64;
    const int kb = blockIdx.z * 256;

    unsigned long long acc[4][4];
#pragma unroll
    for (int r = 0; r < 4; r++)
#pragma unroll
        for (int c = 0; c < 4; c++) acc[r][c] = 0ULL;

    for (int kc = kb; kc < kb + 256; kc += 32) {
#pragma unroll
        for (int u = 0; u < 2; u++) {
            int fi  = t + 128 * u;
            int row = fi >> 3;
            int kq  = fi & 7;
            float4 v = *reinterpret_cast<const float4*>(
                &x[(size_t)(i0 + row) * 1024 + kc + kq * 4]);
            union { float2 f; unsigned long long u; } p0, p1;
            p0.f = make_float2(v.x, v.y);
            p1.f = make_float2(v.z, v.w);
            xs[(2 * kq) * 32 + row]     = p0.u;
            xs[(2 * kq + 1) * 32 + row] = p1.u;
        }
#pragma unroll
        for (int u = 0; u < 4; u++) {
            int fi   = t + 128 * u;
            int wrow = fi >> 3;
            int kq   = fi & 7;
            float4 v = *reinterpret_cast<const float4*>(
                &W1[(size_t)(j0 + wrow) * 1024 + kc + kq * 4]);
            union { float2 f; unsigned long long u; } p0, p1;
            p0.f = make_float2(v.x, v.y);
            p1.f = make_float2(v.z, v.w);
            ws[(2 * kq) * 64 + wrow]     = p0.u;
            ws[(2 * kq + 1) * 64 + wrow] = p1.u;
        }
        __syncthreads();

#pragma unroll
        for (int kp = 0; kp < 16; kp++) {
            unsigned long long a2[4], b2[4];
#pragma unroll
            for (int r = 0; r < 4; r++) a2[r] = xs[kp * 32 + ty + 8 * r];
#pragma unroll
            for (int c = 0; c < 4; c++) b2[c] = ws[kp * 64 + tx + 16 * c];
#pragma unroll
            for (int r = 0; r < 4; r++)
#pragma unroll
                for (int c = 0; c < 4; c++)
                    acc[r][c] = f32x2_fma(a2[r], b2[c], acc[r][c]);
        }
        __syncthreads();
    }

    float* out = &g_z1p[(size_t)blockIdx.z * Z1SZ];
#pragma unroll
    for (int r = 0; r < 4; r++) {
        int row = i0 + ty + 8 * r;
#pragma unroll
        for (int c = 0; c < 4; c++) {
            int col = j0 + tx + 16 * c;
            out[(size_t)row * 128 + col] = hadd2(acc[r][c]);
        }
    }
}

// =====================================================================
// Kernel 2a: z1 = sum(4 partials)+b1 ; h1 = leaky(LN(z1));
//            z2 = h1@W2^T + b2 ; h2 = leaky(LN(z2))
// one warp per row, 8 warps/block, grid 256
// =====================================================================
__global__ __launch_bounds__(256) void enc2a_kernel(
    const float* __restrict__ b1,
    const float* __restrict__ g1, const float* __restrict__ be1,
    const float* __restrict__ W2, const float* __restrict__ b2,
    const float* __restrict__ g2, const float* __restrict__ be2) {
    __shared__ float w2s[128 * 64];      // [k][pair-interleaved cols]
    __shared__ float h1s[8][128];

    const int t = threadIdx.x;
    for (int idx = t; idx < 8192; idx += 256) {
        int col = idx >> 7;
        int k   = idx & 127;
        w2s[k * 64 + (col & 31) * 2 + (col >> 5)] = W2[idx];
    }
    __syncthreads();

    const int lane = t & 31;
    const int w    = t >> 5;
    const int row  = blockIdx.x * 8 + w;
    const size_t off = (size_t)row * 128 + lane * 4;

    float4 p0 = *reinterpret_cast<const float4*>(&g_z1p[0 * Z1SZ + off]);
    float4 p1 = *reinterpret_cast<const float4*>(&g_z1p[1 * Z1SZ + off]);
    float4 p2 = *reinterpret_cast<const float4*>(&g_z1p[2 * Z1SZ + off]);
    float4 p3 = *reinterpret_cast<const float4*>(&g_z1p[3 * Z1SZ + off]);
    float4 bb = *reinterpret_cast<const float4*>(&b1[lane * 4]);
    float4 zv;
    zv.x = (p0.x + p1.x) + (p2.x + p3.x) + bb.x;
    zv.y = (p0.y + p1.y) + (p2.y + p3.y) + bb.y;
    zv.z = (p0.z + p1.z) + (p2.z + p3.z) + bb.z;
    zv.w = (p0.w + p1.w) + (p2.w + p3.w) + bb.w;

    // ---- LN1 + leaky ----
    float s  = zv.x + zv.y + zv.z + zv.w;
    float sq = zv.x * zv.x + zv.y * zv.y + zv.z * zv.z + zv.w * zv.w;
    s  = warp_sum32(s);
    sq = warp_sum32(sq);
    float mu   = s * (1.0f / 128.0f);
    float var  = sq * (1.0f / 128.0f) - mu * mu;
    float rstd = rsqrtf(var + LN_EPS);
    float4 gv  = *reinterpret_cast<const float4*>(&g1[lane * 4]);
    float4 bv  = *reinterpret_cast<const float4*>(&be1[lane * 4]);
    h1s[w][lane * 4 + 0] = leaky((zv.x - mu) * rstd * gv.x + bv.x);
    h1s[w][lane * 4 + 1] = leaky((zv.y - mu) * rstd * gv.y + bv.y);
    h1s[w][lane * 4 + 2] = leaky((zv.z - mu) * rstd * gv.z + bv.z);
    h1s[w][lane * 4 + 3] = leaky((zv.w - mu) * rstd * gv.w + bv.w);
    __syncwarp();

    // ---- GEMM2: 2 cols per lane, 4 partials each ----
    float pa0 = 0.f, pa1 = 0.f, pa2 = 0.f, pa3 = 0.f;
    float pb0 = 0.f, pb1 = 0.f, pb2 = 0.f, pb3 = 0.f;
#pragma unroll
    for (int k4 = 0; k4 < 128; k4 += 4) {
        float4 hv = *reinterpret_cast<const float4*>(&h1s[w][k4]);
        float2 w0 = *reinterpret_cast<const float2*>(&w2s[(k4 + 0) * 64 + lane * 2]);
        float2 w1 = *reinterpret_cast<const float2*>(&w2s[(k4 + 1) * 64 + lane * 2]);
        float2 w2v = *reinterpret_cast<const float2*>(&w2s[(k4 + 2) * 64 + lane * 2]);
        float2 w3 = *reinterpret_cast<const float2*>(&w2s[(k4 + 3) * 64 + lane * 2]);
        pa0 += hv.x * w0.x;  pb0 += hv.x * w0.y;
        pa1 += hv.y * w1.x;  pb1 += hv.y * w1.y;
        pa2 += hv.z * w2v.x; pb2 += hv.z * w2v.y;
        pa3 += hv.w * w3.x;  pb3 += hv.w * w3.y;
    }
    float z2a = (pa0 + pa1) + (pa2 + pa3) + b2[lane];
    float z2b = (pb0 + pb1) + (pb2 + pb3) + b2[lane + 32];

    // ---- LN2 + leaky ----
    float s2  = warp_sum32(z2a + z2b);
    float sq2 = warp_sum32(z2a * z2a + z2b * z2b);
    float mu2   = s2 * (1.0f / 64.0f);
    float var2  = sq2 * (1.0f / 64.0f) - mu2 * mu2;
    float rstd2 = rsqrtf(var2 + LN_EPS);
    g_h2[(size_t)row * 64 + lane]      = leaky((z2a - mu2) * rstd2 * g2[lane] + be2[lane]);
    g_h2[(size_t)row * 64 + lane + 32] = leaky((z2b - mu2) * rstd2 * g2[lane + 32] + be2[lane + 32]);
}

// =====================================================================
// Kernel 2b: z3 = h2@W3^T + b3 ; h3 = leaky(LN(z3)) ; M = (h3 @ T)*log2e
// Also zeroes g_ob. one warp per row, 8 warps/block, grid 256
// =====================================================================
__global__ __launch_bounds__(256) void enc2b_kernel(
    const float* __restrict__ W3, const float* __restrict__ b3,
    const float* __restrict__ g3, const float* __restrict__ be3,
    const float* __restrict__ T) {
    __shared__ float w3t[64 * 32];   // [k][c]
    __shared__ float Ts[32 * 80];    // [k][c]
    __shared__ float h2s[8][64];
    __shared__ float h3s[8][32];

    const int t = threadIdx.x;
    if (t < 40) g_ob[blockIdx.x * 40 + t] = 0.0f;

    for (int idx = t; idx < 2048; idx += 256) {
        int c = idx >> 6;
        int k = idx & 63;
        w3t[k * 32 + c] = W3[idx];
    }
    for (int idx = t; idx < 2560; idx += 256) Ts[idx] = T[idx];
    __syncthreads();

    const int lane = t & 31;
    const int w    = t >> 5;
    const int row  = blockIdx.x * 8 + w;

    float2 h2v = *reinterpret_cast<const float2*>(&g_h2[(size_t)row * 64 + lane * 2]);
    h2s[w][lane * 2]     = h2v.x;
    h2s[w][lane * 2 + 1] = h2v.y;
    __syncwarp();

    float q0 = 0.f, q1 = 0.f, q2 = 0.f, q3 = 0.f;
#pragma unroll
    for (int k = 0; k < 64; k += 4) {
        q0 += h2s[w][k + 0] * w3t[(k + 0) * 32 + lane];
        q1 += h2s[w][k + 1] * w3t[(k + 1) * 32 + lane];
        q2 += h2s[w][k + 2] * w3t[(k + 2) * 32 + lane];
        q3 += h2s[w][k + 3] * w3t[(k + 3) * 32 + lane];
    }
    float z3 = (q0 + q1) + (q2 + q3) + b3[lane];

    float s3  = warp_sum32(z3);
    float sq3 = warp_sum32(z3 * z3);
    float mu3   = s3 * (1.0f / 32.0f);
    float var3  = sq3 * (1.0f / 32.0f) - mu3 * mu3;
    float rstd3 = rsqrtf(var3 + LN_EPS);
    float h3v = leaky((z3 - mu3) * rstd3 * g3[lane] + be3[lane]);
    g_h3[(size_t)row * 32 + lane] = h3v;
    h3s[w][lane] = h3v;
    __syncwarp();

    for (int c = lane; c < 80; c += 32) {
        float m0 = 0.f, m1 = 0.f;
#pragma unroll
        for (int k = 0; k < 32; k += 2) {
            m0 += h3s[w][k]     * Ts[k * 80 + c];
            m1 += h3s[w][k + 1] * Ts[(k + 1) * 80 + c];
        }
        g_M[(size_t)row * 80 + c] = (m0 + m1) * LOG2E;   // pre-scale for ex2
    }
}

// =====================================================================
// Kernel 4: SYMMETRIC pairwise, column-split halves.
// 136 tile pairs x 5 o = 680 blocks, 256 threads (8 warps).
// Half h (t>>7) processes rows 0..127 x columns [64h, 64h+64).
// Row acc: register + 1 atomicAdd per half. Col acc: per-half shfl.
// Diagonal tiles: strict upper triangle only; final kernel drops the -1.
// =====================================================================
#define ABSM 0x7FFFFFFF7FFFFFFFULL

__global__ __launch_bounds__(256) void pairwise_kernel() {
    __shared__ unsigned long long mjneg[128 * 8];
    __shared__ float colacc[8][64];

    const int bid = blockIdx.x;
    const int o   = bid % 5;
    int p = bid / 5;                 // 0..135 upper-triangle pair index
    int it = 0;
    while (p >= 16 - it) { p -= 16 - it; it++; }
    const int jt = it + p;
    const bool diag = (it == jt);
    const int i0 = it * 128;
    const int j0 = jt * 128;
    const int t    = threadIdx.x;
    const int th   = t & 127;        // row owned
    const int half = t >> 7;         // column half
    const int lane = t & 31;
    const int w    = t >> 5;         // 0..7

    // stage j-tile negated (all 256 threads)
    for (int idx = t; idx < 1024; idx += 256) {
        int jj = idx >> 3;
        int pp = idx & 7;
        float2 v = *reinterpret_cast<const float2*>(
            &g_M[(size_t)(j0 + jj) * 80 + o * 16 + pp * 2]);
        union { float2 f; unsigned long long u; } cv;
        cv.f = make_float2(-v.x, -v.y);
        mjneg[jj * 8 + pp] = cv.u;
    }

    unsigned long long mi[8];
#pragma unroll
    for (int pp = 0; pp < 8; pp++)
        mi[pp] = *reinterpret_cast<const unsigned long long*>(
            &g_M[(size_t)(i0 + th) * 80 + o * 16 + pp * 2]);
    __syncthreads();

    const int jbase = half * 64;
    float es = 0.f;
#pragma unroll 2
    for (int d = 0; d < 64; d++) {
        const int jj = jbase + d;
        unsigned long long a0 = 0ULL, a1 = 0ULL;
#pragma unroll
        for (int pp = 0; pp < 8; pp += 2) {
            unsigned long long d0 = f32x2_add(mi[pp],     mjneg[jj * 8 + pp]);
            unsigned long long d1 = f32x2_add(mi[pp + 1], mjneg[jj * 8 + pp + 1]);
            a0 = f32x2_add(a0, d0 & ABSM);
            a1 = f32x2_add(a1, d1 & ABSM);
        }
        unsigned long long at = f32x2_add(a0, a1);
        union { unsigned long long u; float2 f; } cc; cc.u = at;
        float nl1 = -cc.f.x - cc.f.y;
        float e = ex2_approx(nl1);
        if (diag && jj <= th) e = 0.f;       // strict upper triangle only
        es += e;
        // lane reduction for column jj (within this half's 4 warps)
        float cs = e;
        cs += __shfl_xor_sync(0xffffffffu, cs, 16);
        cs += __shfl_xor_sync(0xffffffffu, cs, 8);
        cs += __shfl_xor_sync(0xffffffffu, cs, 4);
        cs += __shfl_xor_sync(0xffffffffu, cs, 2);
        cs += __shfl_xor_sync(0xffffffffu, cs, 1);
        if (lane == 0) colacc[w][d] = cs;
    }
    // row contribution (each half adds its partial)
    atomicAdd(&g_ob[(i0 + th) * 5 + o], es);
    __syncthreads();
    // column contribution: threads 0..127, column c = t
    if (t < 128) {
        int base = (t >> 6) * 4;          // 0 for cols 0-63, 4 for 64-127
        int idx  = t & 63;
        float cs = (colacc[base + 0][idx] + colacc[base + 1][idx]) +
                   (colacc[base + 2][idx] + colacc[base + 3][idx]);
        atomicAdd(&g_ob[(j0 + t) * 5 + o], cs);
    }
}

// =====================================================================
// Kernel 5: out[i] = bf + Wf[0:32].h3[i] + Wf[32:37].ob[i]
// (ob excludes the self term, so no -1)
// =====================================================================
__global__ void final_kernel(const float* __restrict__ Wf,
                             const float* __restrict__ bf,
                             float* __restrict__ out) {
    int i = blockIdx.x * blockDim.x + threadIdx.x;
    if (i >= 2048) return;
    float s = bf[0];
#pragma unroll
    for (int c = 0; c < 32; c++) s += g_h3[(size_t)i * 32 + c] * Wf[c];
#pragma unroll
    for (int oo = 0; oo < 5; oo++) s += g_ob[i * 5 + oo] * Wf[32 + oo];
    out[i] = s;
}

// =====================================================================
extern "C" void kernel_launch(void* const* d_in, const int* in_sizes, int n_in,
                              void* d_out, int out_size) {
    (void)in_sizes; (void)n_in; (void)out_size;
    const float* x   = (const float*)d_in[0];
    const float* W1  = (const float*)d_in[1];
    const float* b1  = (const float*)d_in[2];
    const float* g1  = (const float*)d_in[3];
    const float* be1 = (const float*)d_in[4];
    const float* W2  = (const float*)d_in[5];
    const float* b2  = (const float*)d_in[6];
    const float* g2  = (const float*)d_in[7];
    const float* be2 = (const float*)d_in[8];
    const float* W3  = (const float*)d_in[9];
    const float* b3  = (const float*)d_in[10];
    const float* g3  = (const float*)d_in[11];
    const float* be3 = (const float*)d_in[12];
    const float* T   = (const float*)d_in[13];
    const float* Wf  = (const float*)d_in[14];
    const float* bf  = (const float*)d_in[15];
    float* out = (float*)d_out;

    gemm1_kernel<<<dim3(64, 2, 4), 128>>>(x, W1);
    enc2a_kernel<<<256, 256>>>(b1, g1, be1, W2, b2, g2, be2);
    enc2b_kernel<<<256, 256>>>(W3, b3, g3, be3, T);
    pairwise_kernel<<<680, 256>>>();
    final_kernel<<<8, 256>>>(Wf, bf, out);
}

// round 10
// speedup vs baseline: 1.7219x; 1.3423x over previous
#include <cuda_runtime.h>
#include <cstdint>

#define LN_EPS 1e-5f
#define NEG_SLOPE 0.2f
#define LOG2E 1.4426950408889634f

// ---------------- scratch (no allocations allowed) ----------------
#define Z1SZ (2048 * 128)
__device__ float g_z1p[4 * Z1SZ];    // split-K partials of x@W1^T
__device__ float g_h2[2048 * 64];    // after LN2+leaky
__device__ float g_h3[2048 * 32];    // after LN3+leaky
__device__ float g_M [2048 * 80];    // (h3 @ T) * log2(e)  [pre-scaled]
__device__ float g_ob[2048 * 5];     // pairwise accumulators (no self term)

// ---------------- helpers ----------------
__device__ __forceinline__ unsigned long long f32x2_fma(unsigned long long a,
                                                        unsigned long long b,
                                                        unsigned long long c) {
    unsigned long long d;
    asm("fma.rn.f32x2 %0, %1, %2, %3;" : "=l"(d) : "l"(a), "l"(b), "l"(c));
    return d;
}
__device__ __forceinline__ unsigned long long f32x2_add(unsigned long long a,
                                                        unsigned long long b) {
    unsigned long long d;
    asm("add.rn.f32x2 %0, %1, %2;" : "=l"(d) : "l"(a), "l"(b));
    return d;
}
__device__ __forceinline__ float hadd2(unsigned long long a) {
    union { unsigned long long u; float2 f; } c; c.u = a;
    return c.f.x + c.f.y;
}
__device__ __forceinline__ float warp_sum32(float v) {
    v += __shfl_xor_sync(0xffffffffu, v, 16);
    v += __shfl_xor_sync(0xffffffffu, v, 8);
    v += __shfl_xor_sync(0xffffffffu, v, 4);
    v += __shfl_xor_sync(0xffffffffu, v, 2);
    v += __shfl_xor_sync(0xffffffffu, v, 1);
    return v;
}
__device__ __forceinline__ float leaky(float v) {
    return v >= 0.0f ? v : NEG_SLOPE * v;
}
__device__ __forceinline__ float ex2_approx(float v) {
    float r;
    asm("ex2.approx.f32 %0, %1;" : "=f"(r) : "f"(v));
    return r;
}

// =====================================================================
// Kernel 1: split-K GEMM  z1p[ks] = x @ W1^T  (K slice of 256)
// Tile 32x64, BK=32, 128 threads (8x16), thread tile 4x4, packed f32x2.
// Padded smem strides (33/65 u64, scalar 8B accesses -> always aligned).
// grid (64, 2, 4) = 512 blocks
// =====================================================================
__global__ __launch_bounds__(128) void gemm1_kernel(
    const float* __restrict__ x, const float* __restrict__ W1) {
    __shared__ unsigned long long xs[16 * 33];   // [kp][row], pad 33
    __shared__ unsigned long long ws[16 * 65];   // [kp][col], pad 65

    const int t  = threadIdx.x;
    const int tx = t & 15;          // col group
    const int ty = t >> 4;          // row group
    const int i0 = blockIdx.x * 32;
    const int j0 = blockIdx.y * 64;
    const int kb = blockIdx.z * 256;

    unsigned long long acc[4][4];
#pragma unroll
    for (int r = 0; r < 4; r++)
#pragma unroll
        for (int c = 0; c < 4; c++) acc[r][c] = 0ULL;

    for (int kc = kb; kc < kb + 256; kc += 32) {
#pragma unroll
        for (int u = 0; u < 2; u++) {
            int fi  = t + 128 * u;
            int row = fi >> 3;
            int kq  = fi & 7;
            float4 v = *reinterpret_cast<const float4*>(
                &x[(size_t)(i0 + row) * 1024 + kc + kq * 4]);
            union { float2 f; unsigned long long u; } p0, p1;
            p0.f = make_float2(v.x, v.y);
            p1.f = make_float2(v.z, v.w);
            xs[(2 * kq) * 33 + row]     = p0.u;
            xs[(2 * kq + 1) * 33 + row] = p1.u;
        }
#pragma unroll
        for (int u = 0; u < 4; u++) {
            int fi   = t + 128 * u;
            int wrow = fi >> 3;
            int kq   = fi & 7;
            float4 v = *reinterpret_cast<const float4*>(
                &W1[(size_t)(j0 + wrow) * 1024 + kc + kq * 4]);
            union { float2 f; unsigned long long u; } p0, p1;
            p0.f = make_float2(v.x, v.y);
            p1.f = make_float2(v.z, v.w);
            ws[(2 * kq) * 65 + wrow]     = p0.u;
            ws[(2 * kq + 1) * 65 + wrow] = p1.u;
        }
        __syncthreads();

#pragma unroll
        for (int kp = 0; kp < 16; kp++) {
            unsigned long long a2[4], b2[4];
#pragma unroll
            for (int r = 0; r < 4; r++) a2[r] = xs[kp * 33 + ty + 8 * r];
#pragma unroll
            for (int c = 0; c < 4; c++) b2[c] = ws[kp * 65 + tx + 16 * c];
#pragma unroll
            for (int r = 0; r < 4; r++)
#pragma unroll
                for (int c = 0; c < 4; c++)
                    acc[r][c] = f32x2_fma(a2[r], b2[c], acc[r][c]);
        }
        __syncthreads();
    }

    float* out = &g_z1p[(size_t)blockIdx.z * Z1SZ];
#pragma unroll
    for (int r = 0; r < 4; r++) {
        int row = i0 + ty + 8 * r;
#pragma unroll
        for (int c = 0; c < 4; c++) {
            int col = j0 + tx + 16 * c;
            out[(size_t)row * 128 + col] = hadd2(acc[r][c]);
        }
    }
}

// =====================================================================
// Kernel 2a: z1 = sum(4 partials)+b1 ; h1 = leaky(LN(z1));
//            z2 = h1@W2^T + b2 ; h2 = leaky(LN(z2))
// one warp per row, 8 warps/block, grid 256.
// w2s stride 66 (EVEN: float2 loads stay 8B-aligned; stores 2-way max).
// =====================================================================
#define W2S 66
__global__ __launch_bounds__(256) void enc2a_kernel(
    const float* __restrict__ b1,
    const float* __restrict__ g1, const float* __restrict__ be1,
    const float* __restrict__ W2, const float* __restrict__ b2,
    const float* __restrict__ g2, const float* __restrict__ be2) {
    __shared__ float w2s[128 * W2S];     // [k][pair-interleaved cols], pad 66
    __shared__ float h1s[8][128];

    const int t = threadIdx.x;
    // W2 is [64][128] row-major; k-fast within warp: <=2-way STS conflicts
    for (int idx = t; idx < 8192; idx += 256) {
        int col = idx >> 7;
        int k   = idx & 127;
        w2s[k * W2S + (col & 31) * 2 + (col >> 5)] = W2[idx];
    }
    __syncthreads();

    const int lane = t & 31;
    const int w    = t >> 5;
    const int row  = blockIdx.x * 8 + w;
    const size_t off = (size_t)row * 128 + lane * 4;

    float4 p0 = *reinterpret_cast<const float4*>(&g_z1p[0 * Z1SZ + off]);
    float4 p1 = *reinterpret_cast<const float4*>(&g_z1p[1 * Z1SZ + off]);
    float4 p2 = *reinterpret_cast<const float4*>(&g_z1p[2 * Z1SZ + off]);
    float4 p3 = *reinterpret_cast<const float4*>(&g_z1p[3 * Z1SZ + off]);
    float4 bb = *reinterpret_cast<const float4*>(&b1[lane * 4]);
    float4 zv;
    zv.x = (p0.x + p1.x) + (p2.x + p3.x) + bb.x;
    zv.y = (p0.y + p1.y) + (p2.y + p3.y) + bb.y;
    zv.z = (p0.z + p1.z) + (p2.z + p3.z) + bb.z;
    zv.w = (p0.w + p1.w) + (p2.w + p3.w) + bb.w;

    // ---- LN1 + leaky ----
    float s  = zv.x + zv.y + zv.z + zv.w;
    float sq = zv.x * zv.x + zv.y * zv.y + zv.z * zv.z + zv.w * zv.w;
    s  = warp_sum32(s);
    sq = warp_sum32(sq);
    float mu   = s * (1.0f / 128.0f);
    float var  = sq * (1.0f / 128.0f) - mu * mu;
    float rstd = rsqrtf(var + LN_EPS);
    float4 gv  = *reinterpret_cast<const float4*>(&g1[lane * 4]);
    float4 bv  = *reinterpret_cast<const float4*>(&be1[lane * 4]);
    h1s[w][lane * 4 + 0] = leaky((zv.x - mu) * rstd * gv.x + bv.x);
    h1s[w][lane * 4 + 1] = leaky((zv.y - mu) * rstd * gv.y + bv.y);
    h1s[w][lane * 4 + 2] = leaky((zv.z - mu) * rstd * gv.z + bv.z);
    h1s[w][lane * 4 + 3] = leaky((zv.w - mu) * rstd * gv.w + bv.w);
    __syncwarp();

    // ---- GEMM2: 2 cols per lane, 4 partials each ----
    float pa0 = 0.f, pa1 = 0.f, pa2 = 0.f, pa3 = 0.f;
    float pb0 = 0.f, pb1 = 0.f, pb2 = 0.f, pb3 = 0.f;
#pragma unroll
    for (int k4 = 0; k4 < 128; k4 += 4) {
        float4 hv = *reinterpret_cast<const float4*>(&h1s[w][k4]);
        float2 w0 = *reinterpret_cast<const float2*>(&w2s[(k4 + 0) * W2S + lane * 2]);
        float2 w1 = *reinterpret_cast<const float2*>(&w2s[(k4 + 1) * W2S + lane * 2]);
        float2 w2v = *reinterpret_cast<const float2*>(&w2s[(k4 + 2) * W2S + lane * 2]);
        float2 w3 = *reinterpret_cast<const float2*>(&w2s[(k4 + 3) * W2S + lane * 2]);
        pa0 += hv.x * w0.x;  pb0 += hv.x * w0.y;
        pa1 += hv.y * w1.x;  pb1 += hv.y * w1.y;
        pa2 += hv.z * w2v.x; pb2 += hv.z * w2v.y;
        pa3 += hv.w * w3.x;  pb3 += hv.w * w3.y;
    }
    float z2a = (pa0 + pa1) + (pa2 + pa3) + b2[lane];
    float z2b = (pb0 + pb1) + (pb2 + pb3) + b2[lane + 32];

    // ---- LN2 + leaky ----
    float s2  = warp_sum32(z2a + z2b);
    float sq2 = warp_sum32(z2a * z2a + z2b * z2b);
    float mu2   = s2 * (1.0f / 64.0f);
    float var2  = sq2 * (1.0f / 64.0f) - mu2 * mu2;
    float rstd2 = rsqrtf(var2 + LN_EPS);
    g_h2[(size_t)row * 64 + lane]      = leaky((z2a - mu2) * rstd2 * g2[lane] + be2[lane]);
    g_h2[(size_t)row * 64 + lane + 32] = leaky((z2b - mu2) * rstd2 * g2[lane + 32] + be2[lane + 32]);
}

// =====================================================================
// Kernel 2b: z3 = h2@W3^T + b3 ; h3 = leaky(LN(z3)) ; M = (h3 @ T)*log2e
// Also zeroes g_ob. one warp per row, 8 warps/block, grid 256.
// w3t stride 33 (scalar float access only; conflict-free).
// =====================================================================
__global__ __launch_bounds__(256) void enc2b_kernel(
    const float* __restrict__ W3, const float* __restrict__ b3,
    const float* __restrict__ g3, const float* __restrict__ be3,
    const float* __restrict__ T) {
    __shared__ float w3t[64 * 33];   // [k][c], pad 33
    __shared__ float Ts[32 * 80];    // [k][c]
    __shared__ float h2s[8][64];
    __shared__ float h3s[8][32];

    const int t = threadIdx.x;
    if (t < 40) g_ob[blockIdx.x * 40 + t] = 0.0f;

    for (int idx = t; idx < 2048; idx += 256) {
        int c = idx >> 6;
        int k = idx & 63;
        w3t[k * 33 + c] = W3[idx];
    }
    for (int idx = t; idx < 2560; idx += 256) Ts[idx] = T[idx];
    __syncthreads();

    const int lane = t & 31;
    const int w    = t >> 5;
    const int row  = blockIdx.x * 8 + w;

    float2 h2v = *reinterpret_cast<const float2*>(&g_h2[(size_t)row * 64 + lane * 2]);
    h2s[w][lane * 2]     = h2v.x;
    h2s[w][lane * 2 + 1] = h2v.y;
    __syncwarp();

    float q0 = 0.f, q1 = 0.f, q2 = 0.f, q3 = 0.f;
#pragma unroll
    for (int k = 0; k < 64; k += 4) {
        q0 += h2s[w][k + 0] * w3t[(k + 0) * 33 + lane];
        q1 += h2s[w][k + 1] * w3t[(k + 1) * 33 + lane];
        q2 += h2s[w][k + 2] * w3t[(k + 2) * 33 + lane];
        q3 += h2s[w][k + 3] * w3t[(k + 3) * 33 + lane];
    }
    float z3 = (q0 + q1) + (q2 + q3) + b3[lane];

    float s3  = warp_sum32(z3);
    float sq3 = warp_sum32(z3 * z3);
    float mu3   = s3 * (1.0f / 32.0f);
    float var3  = sq3 * (1.0f / 32.0f) - mu3 * mu3;
    float rstd3 = rsqrtf(var3 + LN_EPS);
    float h3v = leaky((z3 - mu3) * rstd3 * g3[lane] + be3[lane]);
    g_h3[(size_t)row * 32 + lane] = h3v;
    h3s[w][lane] = h3v;
    __syncwarp();

    for (int c = lane; c < 80; c += 32) {
        float m0 = 0.f, m1 = 0.f;
#pragma unroll
        for (int k = 0; k < 32; k += 2) {
            m0 += h3s[w][k]     * Ts[k * 80 + c];
            m1 += h3s[w][k + 1] * Ts[(k + 1) * 80 + c];
        }
        g_M[(size_t)row * 80 + c] = (m0 + m1) * LOG2E;   // pre-scale for ex2
    }
}

// =====================================================================
// Kernel 4: SYMMETRIC pairwise, pair-merged SHFL column reduction.
// 136 tile pairs x 5 o = 680 blocks, 256 threads (8 warps).
// Thread: row th = t&127, column half = t>>7 (64 cols).
// Columns processed 2 per reduction round: first xor-1 exchange muxes
// (e0,e1) by lane parity, then 4 more xor levels; even lanes end with
// col0's full sum, odd lanes with col1's -> lanes 0,1 STS (once per col).
// Diagonal tiles run a separate masked loop. Final kernel drops the -1.
// =====================================================================
#define ABSM 0x7FFFFFFF7FFFFFFFULL

__global__ __launch_bounds__(256) void pairwise_kernel() {
    __shared__ unsigned long long mjneg[128 * 8];
    __shared__ float colpart[8][64];

    const int bid = blockIdx.x;
    const int o   = bid % 5;
    int p = bid / 5;                 // 0..135 upper-triangle pair index
    int it = 0;
    while (p >= 16 - it) { p -= 16 - it; it++; }
    const int jt = it + p;
    const bool diag = (it == jt);
    const int i0 = it * 128;
    const int j0 = jt * 128;
    const int t    = threadIdx.x;
    const int th   = t & 127;        // row owned
    const int half = t >> 7;         // column half
    const int lane = t & 31;
    const int w    = t >> 5;         // 0..7

    // stage j-tile negated (all 256 threads)
    for (int idx = t; idx < 1024; idx += 256) {
        int jj = idx >> 3;
        int pp = idx & 7;
        float2 v = *reinterpret_cast<const float2*>(
            &g_M[(size_t)(j0 + jj) * 80 + o * 16 + pp * 2]);
        union { float2 f; unsigned long long u; } cv;
        cv.f = make_float2(-v.x, -v.y);
        mjneg[jj * 8 + pp] = cv.u;
    }

    unsigned long long mi[8];
#pragma unroll
    for (int pp = 0; pp < 8; pp++)
        mi[pp] = *reinterpret_cast<const unsigned long long*>(
            &g_M[(size_t)(i0 + th) * 80 + o * 16 + pp * 2]);
    __syncthreads();

    const int jbase = half * 64;
    float es = 0.f;

#define PW_EVAL(JJ, E)                                                      \
    {                                                                       \
        const unsigned long long* mjp = &mjneg[(JJ) * 8];                   \
        unsigned long long a0 = 0ULL, a1 = 0ULL;                            \
        _Pragma("unroll")                                                   \
        for (int pp = 0; pp < 8; pp += 2) {                                 \
            unsigned long long d0 = f32x2_add(mi[pp],     mjp[pp]);         \
            unsigned long long d1 = f32x2_add(mi[pp + 1], mjp[pp + 1]);     \
            a0 = f32x2_add(a0, d0 & ABSM);                                  \
            a1 = f32x2_add(a1, d1 & ABSM);                                  \
        }                                                                   \
        unsigned long long at = f32x2_add(a0, a1);                          \
        union { unsigned long long u; float2 f; } cc; cc.u = at;            \
        E = ex2_approx(-cc.f.x - cc.f.y);                                   \
    }

#define PW_REDUCE2(E0, E1, D2)                                              \
    {                                                                       \
        float tm = (lane & 1) ? (E0) : (E1);                                \
        tm = __shfl_xor_sync(0xffffffffu, tm, 1);                           \
        float sm = ((lane & 1) ? (E1) : (E0)) + tm;                         \
        sm += __shfl_xor_sync(0xffffffffu, sm, 2);                          \
        sm += __shfl_xor_sync(0xffffffffu, sm, 4);                          \
        sm += __shfl_xor_sync(0xffffffffu, sm, 8);                          \
        sm += __shfl_xor_sync(0xffffffffu, sm, 16);                         \
        if (lane < 2) colpart[w][2 * (D2) + lane] = sm;                     \
    }

    if (!diag) {
#pragma unroll 4
        for (int d2 = 0; d2 < 32; d2++) {
            float e0, e1;
            PW_EVAL(jbase + 2 * d2,     e0);
            PW_EVAL(jbase + 2 * d2 + 1, e1);
            es += e0 + e1;
            PW_REDUCE2(e0, e1, d2);
        }
    } else {
#pragma unroll 4
        for (int d2 = 0; d2 < 32; d2++) {
            int jj = jbase + 2 * d2;
            float e0, e1;
            PW_EVAL(jj,     e0);
            PW_EVAL(jj + 1, e1);
            if (jj     <= th) e0 = 0.f;     // strict upper triangle only
            if (jj + 1 <= th) e1 = 0.f;
            es += e0 + e1;
            PW_REDUCE2(e0, e1, d2);
        }
    }
#undef PW_EVAL
#undef PW_REDUCE2

    // row contribution (each half adds its partial)
    atomicAdd(&g_ob[(i0 + th) * 5 + o], es);
    __syncthreads();
    // column contribution: thread t<128 handles column c=t of the j-tile
    if (t < 128) {
        int wb  = (t >> 6) * 4;          // warps 0-3 own cols 0-63, 4-7 own 64-127
        int idx = t & 63;
        float cs = (colpart[wb + 0][idx] + colpart[wb + 1][idx]) +
                   (colpart[wb + 2][idx] + colpart[wb + 3][idx]);
        atomicAdd(&g_ob[(j0 + t) * 5 + o], cs);
    }
}

// =====================================================================
// Kernel 5: out[i] = bf + Wf[0:32].h3[i] + Wf[32:37].ob[i]
// (ob excludes the self term, so no -1)
// =====================================================================
__global__ void final_kernel(const float* __restrict__ Wf,
                             const float* __restrict__ bf,
                             float* __restrict__ out) {
    int i = blockIdx.x * blockDim.x + threadIdx.x;
    if (i >= 2048) return;
    float s = bf[0];
#pragma unroll
    for (int c = 0; c < 32; c++) s += g_h3[(size_t)i * 32 + c] * Wf[c];
#pragma unroll
    for (int oo = 0; oo < 5; oo++) s += g_ob[i * 5 + oo] * Wf[32 + oo];
    out[i] = s;
}

// =====================================================================
extern "C" void kernel_launch(void* const* d_in, const int* in_sizes, int n_in,
                              void* d_out, int out_size) {
    (void)in_sizes; (void)n_in; (void)out_size;
    const float* x   = (const float*)d_in[0];
    const float* W1  = (const float*)d_in[1];
    const float* b1  = (const float*)d_in[2];
    const float* g1  = (const float*)d_in[3];
    const float* be1 = (const float*)d_in[4];
    const float* W2  = (const float*)d_in[5];
    const float* b2  = (const float*)d_in[6];
    const float* g2  = (const float*)d_in[7];
    const float* be2 = (const float*)d_in[8];
    const float* W3  = (const float*)d_in[9];
    const float* b3  = (const float*)d_in[10];
    const float* g3  = (const float*)d_in[11];
    const float* be3 = (const float*)d_in[12];
    const float* T   = (const float*)d_in[13];
    const float* Wf  = (const float*)d_in[14];
    const float* bf  = (const float*)d_in[15];
    float* out = (float*)d_out;

    gemm1_kernel<<<dim3(64, 2, 4), 128>>>(x, W1);
    enc2a_kernel<<<256, 256>>>(b1, g1, be1, W2, b2, g2, be2);
    enc2b_kernel<<<256, 256>>>(W3, b3, g3, be3, T);
    pairwise_kernel<<<680, 256>>>();
    final_kernel<<<8, 256>>>(Wf, bf, out);
}